// round 1
// baseline (speedup 1.0000x reference)
#include <cuda_runtime.h>
#include <cuda_bf16.h>
#include <cstdint>

// Problem constants
#define BB   8
#define CIN  64
#define COUT 64
#define HH   512
#define WW   512
#define KK   3

// Conv tiling: block = 256 threads, output tile = 64 couts x (8 rows x 32 cols)
// thread: cout-group (8 couts) x micro-tile (2 rows x 4 cols, packed as f32x2 col pairs)

// Demodulated weights, layout [b][cin][kk][cout]  (cout fastest for coalesced loads)
__device__ float g_wmod[BB * CIN * KK * KK * COUT];

// ---------------------------------------------------------------------------
// f32x2 helpers (Blackwell packed fp32: FFMA2 via PTX fma.rn.f32x2)
// ---------------------------------------------------------------------------
__device__ __forceinline__ unsigned long long pack2(float lo, float hi) {
    unsigned long long r;
    asm("mov.b64 %0, {%1, %2};" : "=l"(r)
        : "r"(__float_as_uint(lo)), "r"(__float_as_uint(hi)));
    return r;
}

__device__ __forceinline__ void unpack2(unsigned long long v, float& lo, float& hi) {
    unsigned int a, b;
    asm("mov.b64 {%0, %1}, %2;" : "=r"(a), "=r"(b) : "l"(v));
    lo = __uint_as_float(a);
    hi = __uint_as_float(b);
}

__device__ __forceinline__ unsigned long long ffma2(unsigned long long a,
                                                    unsigned long long b,
                                                    unsigned long long c) {
    unsigned long long d;
    asm("fma.rn.f32x2 %0, %1, %2, %3;" : "=l"(d) : "l"(a), "l"(b), "l"(c));
    return d;
}

// ---------------------------------------------------------------------------
// Kernel 1: modulate + demodulate weights.
// grid (COUT, B), 64 threads (one per cin).
// ---------------------------------------------------------------------------
__global__ void modulate_kernel(const float* __restrict__ w,
                                const float* __restrict__ weight) {
    const int cout = blockIdx.x;
    const int b    = blockIdx.y;
    const int cin  = threadIdx.x;

    const float scale = 1.0f / 24.0f;  // 1/sqrt(64*9)
    const float wv = w[b * CIN + cin] * scale;

    float v[9];
    float ss = 0.0f;
#pragma unroll
    for (int kk = 0; kk < 9; ++kk) {
        float t = weight[(cout * CIN + cin) * 9 + kk] * wv;
        v[kk] = t;
        ss += t * t;
    }

    __shared__ float red[64];
    red[cin] = ss;
    __syncthreads();
    if (cin < 32) {
        float s = red[cin] + red[cin + 32];
#pragma unroll
        for (int off = 16; off > 0; off >>= 1)
            s += __shfl_down_sync(0xffffffffu, s, off);
        if (cin == 0) red[0] = s;
    }
    __syncthreads();

    const float d = rsqrtf(red[0] + 1e-8f);
#pragma unroll
    for (int kk = 0; kk < 9; ++kk)
        g_wmod[((b * CIN + cin) * 9 + kk) * COUT + cout] = v[kk] * d;
}

// ---------------------------------------------------------------------------
// Kernel 2: direct conv.
// grid (W/32=16, H/8=64, B=8), 256 threads.
//   warp id (tid>>5)  = cout group cg (couts cg*8 .. cg*8+7)
//   lane p = tid&31:  px = p&7 (col base px*4), py = p>>3 (row base py*2)
// Per-thread accumulators: [2 rows][2 col-pairs][8 couts] f32x2.
// ---------------------------------------------------------------------------
__global__ void __launch_bounds__(256, 1)
conv_kernel(const float* __restrict__ x, float* __restrict__ out) {
    const int b   = blockIdx.z;
    const int by0 = blockIdx.y * 8;    // output row base
    const int bx0 = blockIdx.x * 32;   // output col base

    const int tid = threadIdx.x;
    const int cg  = tid >> 5;          // 0..7  cout group
    const int p   = tid & 31;
    const int px  = p & 7;             // 0..7
    const int py  = p >> 3;            // 0..3
    const int R0  = py << 1;           // local smem row base (rows R0..R0+3)
    const int C0  = px << 2;           // local smem col base (cols C0..C0+5)
    const int cgbase = cg << 3;

    // smem: x tile with halo (8 cins x 10 rows x 34 cols, padded to 35)
    //       weights duplicated as f32x2 (8 cins x 9 taps x 64 couts)
    __shared__ float sx[8][10][35];                       // 11200 B
    __shared__ unsigned long long sw2[8][9][COUT];        // 36864 B

    unsigned long long acc[2][2][8];
#pragma unroll
    for (int r = 0; r < 2; ++r)
#pragma unroll
        for (int j = 0; j < 2; ++j)
#pragma unroll
            for (int c = 0; c < 8; ++c) acc[r][j][c] = 0ull;

    const float* xb = x + (size_t)b * CIN * HH * WW;

    for (int ch = 0; ch < CIN / 8; ++ch) {
        const int cbase = ch * 8;

        // ---- fill x smem (zero-padded halo) ----
        for (int i = tid; i < 8 * 10 * 34; i += 256) {
            const int cc  = i / 340;
            const int rem = i - cc * 340;
            const int r   = rem / 34;
            const int c   = rem - r * 34;
            const int gy  = by0 + r - 1;
            const int gx  = bx0 + c - 1;
            float v = 0.0f;
            if ((unsigned)gy < (unsigned)HH && (unsigned)gx < (unsigned)WW)
                v = xb[((size_t)(cbase + cc) * HH + gy) * WW + gx];
            sx[cc][r][c] = v;
        }

        // ---- fill duplicated weight smem (coalesced read) ----
        const float* wsrc = g_wmod + ((size_t)(b * CIN + cbase) * 9) * COUT;
        for (int i = tid; i < 8 * 9 * COUT; i += 256) {
            const float wv = wsrc[i];
            const int cc  = i / (9 * COUT);
            const int rem = i - cc * (9 * COUT);
            const int kk  = rem / COUT;
            const int co  = rem - kk * COUT;
            sw2[cc][kk][co] = pack2(wv, wv);
        }
        __syncthreads();

        // ---- compute ----
#pragma unroll 1
        for (int cc = 0; cc < 8; ++cc) {
            // shifted-pair registers: xp[r][p] = (x[C0+p], x[C0+p+1]) for rows R0..R0+3
            unsigned long long xp[4][5];
#pragma unroll
            for (int r = 0; r < 4; ++r) {
                float a = sx[cc][R0 + r][C0];
#pragma unroll
                for (int q = 0; q < 5; ++q) {
                    const float nb = sx[cc][R0 + r][C0 + q + 1];
                    xp[r][q] = pack2(a, nb);
                    a = nb;
                }
            }
#pragma unroll
            for (int kk = 0; kk < 9; ++kk) {
                const int dy = kk / 3;
                const int dx = kk - dy * 3;
#pragma unroll
                for (int co = 0; co < 8; ++co) {
                    const unsigned long long wp = sw2[cc][kk][cgbase + co];
                    acc[0][0][co] = ffma2(xp[0 + dy][0 + dx], wp, acc[0][0][co]);
                    acc[0][1][co] = ffma2(xp[0 + dy][2 + dx], wp, acc[0][1][co]);
                    acc[1][0][co] = ffma2(xp[1 + dy][0 + dx], wp, acc[1][0][co]);
                    acc[1][1][co] = ffma2(xp[1 + dy][2 + dx], wp, acc[1][1][co]);
                }
            }
        }
        __syncthreads();
    }

    // ---- epilogue: float4 stores ----
#pragma unroll
    for (int co = 0; co < 8; ++co) {
        const int cout = cgbase + co;
#pragma unroll
        for (int rr = 0; rr < 2; ++rr) {
            const int gy = by0 + R0 + rr;
            float4 v;
            unpack2(acc[rr][0][co], v.x, v.y);
            unpack2(acc[rr][1][co], v.z, v.w);
            float* dst = out + (((size_t)(b * COUT + cout) * HH + gy) * WW + bx0 + C0);
            *reinterpret_cast<float4*>(dst) = v;
        }
    }
}

// ---------------------------------------------------------------------------
extern "C" void kernel_launch(void* const* d_in, const int* in_sizes, int n_in,
                              void* d_out, int out_size) {
    const float* x      = (const float*)d_in[0];   // [8,64,512,512]
    const float* w      = (const float*)d_in[1];   // [8,64]
    const float* weight = (const float*)d_in[2];   // [64,64,3,3]
    float* out = (float*)d_out;                    // [8,64,512,512]

    modulate_kernel<<<dim3(COUT, BB), 64>>>(w, weight);
    conv_kernel<<<dim3(WW / 32, HH / 8, BB), 256>>>(x, out);
}

// round 3
// speedup vs baseline: 2.4719x; 2.4719x over previous
#include <cuda_runtime.h>
#include <cstdint>

// Problem constants
#define BB    8
#define CINN  64
#define COUTN 64
#define HH    512
#define WWW   512

// Demodulated weights: [b][tap(9)][cout][cin]
__device__ float g_wmod[BB * 9 * COUTN * CINN];

__device__ __forceinline__ uint32_t f2tf32(float f) {
    uint32_t r;
    asm("cvt.rna.tf32.f32 %0, %1;" : "=r"(r) : "f"(f));
    return r;
}

__device__ __forceinline__ void mma_tf32(float* d,
                                         uint32_t a0, uint32_t a1, uint32_t a2, uint32_t a3,
                                         uint32_t b0, uint32_t b1) {
    asm("mma.sync.aligned.m16n8k8.row.col.f32.tf32.tf32.f32 "
        "{%0,%1,%2,%3},{%4,%5,%6,%7},{%8,%9},{%0,%1,%2,%3};"
        : "+f"(d[0]), "+f"(d[1]), "+f"(d[2]), "+f"(d[3])
        : "r"(a0), "r"(a1), "r"(a2), "r"(a3), "r"(b0), "r"(b1));
}

// ---------------------------------------------------------------------------
// Kernel 1: modulate + demodulate weights -> g_wmod[b][tap][cout][cin]
// ---------------------------------------------------------------------------
__global__ void modulate_kernel(const float* __restrict__ w,
                                const float* __restrict__ weight) {
    const int cout = blockIdx.x;
    const int b    = blockIdx.y;
    const int cin  = threadIdx.x;

    const float scale = 1.0f / 24.0f;  // 1/sqrt(64*9)
    const float wv = w[b * CINN + cin] * scale;

    float v[9];
    float ss = 0.0f;
#pragma unroll
    for (int kk = 0; kk < 9; ++kk) {
        float t = weight[(cout * CINN + cin) * 9 + kk] * wv;
        v[kk] = t;
        ss += t * t;
    }

    __shared__ float red[64];
    red[cin] = ss;
    __syncthreads();
    if (cin < 32) {
        float s = red[cin] + red[cin + 32];
#pragma unroll
        for (int off = 16; off > 0; off >>= 1)
            s += __shfl_down_sync(0xffffffffu, s, off);
        if (cin == 0) red[0] = s;
    }
    __syncthreads();

    const float d = rsqrtf(red[0] + 1e-8f);
#pragma unroll
    for (int kk = 0; kk < 9; ++kk)
        g_wmod[((b * 9 + kk) * COUTN + cout) * CINN + cin] = v[kk] * d;
}

// ---------------------------------------------------------------------------
// Kernel 2: TF32 mma.sync implicit-GEMM conv.
// grid (W/256=2, H=512, B=8), 256 threads (8 warps).
// CTA tile: 64 couts (M) x 256 pixels (N) of one output row.
// Warp: 32 couts (2 m-tiles of 16) x 64 px (8 n-tiles of 8).
// K loop: 8 cin-chunks x 9 taps, K=8 per mma (cins k-pair interleaved: t, t+4).
//
// SMEM placement uses pair-rotation so every fragment is a conflict-free
// LDS.64:
//   sx:  word((row,px,pair t,e)) = (row*258+px)*8 + ((t+(px>>2))&3)*2 + e
//   sw:  word((tap,cout,pair t,e)) = (tap*64+cout)*8 + ((t+cout)&3)*2 + e
// ---------------------------------------------------------------------------
__global__ void __launch_bounds__(256, 2)
conv_mma_kernel(const float* __restrict__ x, float* __restrict__ out) {
    __shared__ float sx[3 * 258 * 8];   // 24768 B: 3 input rows x 258 px x 8 cin-slots
    __shared__ float sw[9 * 64 * 8];    // 18432 B: 9 taps x 64 cout x 8 cin-slots

    const int b  = blockIdx.z;
    const int y  = blockIdx.y;
    const int x0 = blockIdx.x * 256;

    const int tid    = threadIdx.x;
    const int wid    = tid >> 5;
    const int lane   = tid & 31;
    const int t      = lane & 3;    // k-pair index / frag thread-in-group
    const int g      = lane >> 2;   // frag group (row/col index)
    const int warp_m = wid & 1;     // cout half
    const int warp_n = wid >> 1;    // pixel quarter

    float acc[2][8][4];
#pragma unroll
    for (int mt = 0; mt < 2; ++mt)
#pragma unroll
        for (int nt = 0; nt < 8; ++nt)
#pragma unroll
            for (int i = 0; i < 4; ++i) acc[mt][nt][i] = 0.0f;

    const float* wsrc = g_wmod + (size_t)b * 9 * COUTN * CINN;

#pragma unroll 1
    for (int ch = 0; ch < 8; ++ch) {
        const int cb = ch * 8;

        // ---- fill sx: 24 (row, cin) planes, 258 px each ----
#pragma unroll 1
        for (int plane = wid; plane < 24; plane += 8) {
            const int row = plane >> 3;
            const int c   = plane & 7;         // cin within chunk (== pair + 4*elem)
            const int pr  = c & 3;
            const int e   = c >> 2;
            const int yy  = y + row - 1;
            const bool yok = ((unsigned)yy < (unsigned)HH);
            const float* src =
                x + (((size_t)(b * CINN + cb + c)) * HH + (yok ? yy : 0)) * WWW;
#pragma unroll
            for (int j = 0; j < 9; ++j) {
                const int px = lane + 32 * j;
                if (px < 258) {
                    const int gx = x0 - 1 + px;
                    float v = 0.0f;
                    if (yok && (unsigned)gx < (unsigned)WWW) v = src[gx];
                    sx[(row * 258 + px) * 8 + ((pr + (px >> 2)) & 3) * 2 + e] =
                        __uint_as_float(f2tf32(v));
                }
            }
        }

        // ---- fill sw: 9 taps x 64 cout x 8 cin-slots ----
#pragma unroll 1
        for (int idx = tid; idx < 9 * 64 * 8; idx += 256) {
            const int s    = idx & 7;
            const int cout = (idx >> 3) & 63;
            const int tap  = idx >> 9;
            const int cin  = (s >> 1) + ((s & 1) << 2);   // pair + 4*elem
            const float v  = wsrc[((size_t)tap * COUTN + cout) * CINN + cb + cin];
            sw[(tap * 64 + cout) * 8 + (((s >> 1) + cout) & 3) * 2 + (s & 1)] =
                __uint_as_float(f2tf32(v));
        }

        __syncthreads();

        // ---- compute: 9 taps of K=8 ----
#pragma unroll
        for (int tap = 0; tap < 9; ++tap) {
            const int dy = tap / 3;
            const int dx = tap - dy * 3;

            // A fragments (weights): 2 m-tiles
            uint32_t A[2][4];
#pragma unroll
            for (int mt = 0; mt < 2; ++mt) {
                const int cout = warp_m * 32 + mt * 16 + g;
                const float2 lo = *(const float2*)
                    &sw[(tap * 64 + cout) * 8 + ((t + cout) & 3) * 2];
                const float2 hi = *(const float2*)
                    &sw[(tap * 64 + cout + 8) * 8 + ((t + cout + 8) & 3) * 2];
                A[mt][0] = __float_as_uint(lo.x);
                A[mt][2] = __float_as_uint(lo.y);
                A[mt][1] = __float_as_uint(hi.x);
                A[mt][3] = __float_as_uint(hi.y);
            }

            // B fragments (x) per n-tile, 2 mmas each
#pragma unroll
            for (int nt = 0; nt < 8; ++nt) {
                const int px = warp_n * 64 + nt * 8 + g + dx;  // sx index (0 = x0-1)
                const float2 bb = *(const float2*)
                    &sx[(dy * 258 + px) * 8 + ((t + (px >> 2)) & 3) * 2];
                const uint32_t b0 = __float_as_uint(bb.x);
                const uint32_t b1 = __float_as_uint(bb.y);
                mma_tf32(acc[0][nt], A[0][0], A[0][1], A[0][2], A[0][3], b0, b1);
                mma_tf32(acc[1][nt], A[1][0], A[1][1], A[1][2], A[1][3], b0, b1);
            }
        }

        __syncthreads();
    }

    // ---- epilogue: float2 stores ----
#pragma unroll
    for (int mt = 0; mt < 2; ++mt) {
        const int cout0 = warp_m * 32 + mt * 16 + g;
#pragma unroll
        for (int nt = 0; nt < 8; ++nt) {
            const int px = x0 + warp_n * 64 + nt * 8 + 2 * t;
            float* p0 = out + (((size_t)(b * COUTN + cout0)) * HH + y) * WWW + px;
            float* p1 = out + (((size_t)(b * COUTN + cout0 + 8)) * HH + y) * WWW + px;
            *(float2*)p0 = make_float2(acc[mt][nt][0], acc[mt][nt][1]);
            *(float2*)p1 = make_float2(acc[mt][nt][2], acc[mt][nt][3]);
        }
    }
}

// ---------------------------------------------------------------------------
extern "C" void kernel_launch(void* const* d_in, const int* in_sizes, int n_in,
                              void* d_out, int out_size) {
    const float* x      = (const float*)d_in[0];   // [8,64,512,512]
    const float* w      = (const float*)d_in[1];   // [8,64]
    const float* weight = (const float*)d_in[2];   // [64,64,3,3]
    float* out = (float*)d_out;                    // [8,64,512,512]

    modulate_kernel<<<dim3(COUTN, BB), 64>>>(w, weight);
    conv_mma_kernel<<<dim3(WWW / 256, HH, BB), 256>>>(x, out);
}

// round 4
// speedup vs baseline: 4.0784x; 1.6499x over previous
#include <cuda_runtime.h>
#include <cstdint>

// Problem constants
#define BB    8
#define CINN  64
#define COUTN 64
#define HH    512
#define WWW   512

#define SEG        256                  // output pixels per CTA
#define SX_BYTES   (3 * 258 * 8 * 4)    // 24768: 3 rows x 258 px x 8 k-slots
#define SW_BYTES   (9 * 64 * 8 * 4)     // 18432: 9 taps x 64 cout x 8 k-slots
#define STAGE_BYTES (SX_BYTES + SW_BYTES)  // 43200
#define SMEM_DYN   (2 * STAGE_BYTES)       // 86400

// Pre-demodulated tf32 weights, prearranged in smem layout:
// [b][ch(8)][tap(9)][cout(64)][slot(8)]   slot = 2*(j&3)+(j>>2), j = cin&7
__device__ float g_wsw[BB * 8 * 9 * COUTN * 8];

// ---------------------------------------------------------------------------
// helpers
// ---------------------------------------------------------------------------
__device__ __forceinline__ uint32_t smem_u32(const void* p) {
    uint32_t a;
    asm("{ .reg .u64 t; cvta.to.shared.u64 t, %1; cvt.u32.u64 %0, t; }" : "=r"(a) : "l"(p));
    return a;
}
__device__ __forceinline__ uint32_t f2tf32(float f) {
    uint32_t r;
    asm("cvt.rna.tf32.f32 %0, %1;" : "=r"(r) : "f"(f));
    return r;
}
__device__ __forceinline__ void cp16(uint32_t d, const void* s) {
    asm volatile("cp.async.cg.shared.global [%0], [%1], 16;" :: "r"(d), "l"(s) : "memory");
}
__device__ __forceinline__ void cp4(uint32_t d, const void* s, uint32_t sz) {
    asm volatile("cp.async.ca.shared.global [%0], [%1], 4, %2;"
                 :: "r"(d), "l"(s), "r"(sz) : "memory");
}
__device__ __forceinline__ void cp_commit() {
    asm volatile("cp.async.commit_group;" ::: "memory");
}
template <int N>
__device__ __forceinline__ void cp_wait() {
    asm volatile("cp.async.wait_group %0;" :: "n"(N) : "memory");
}
__device__ __forceinline__ float2 lds64(uint32_t a) {
    float2 v;
    asm volatile("ld.shared.v2.f32 {%0,%1}, [%2];" : "=f"(v.x), "=f"(v.y) : "r"(a));
    return v;
}
__device__ __forceinline__ void mma_tf32(float* d,
                                         uint32_t a0, uint32_t a1, uint32_t a2, uint32_t a3,
                                         uint32_t b0, uint32_t b1) {
    asm("mma.sync.aligned.m16n8k8.row.col.f32.tf32.tf32.f32 "
        "{%0,%1,%2,%3},{%4,%5,%6,%7},{%8,%9},{%0,%1,%2,%3};"
        : "+f"(d[0]), "+f"(d[1]), "+f"(d[2]), "+f"(d[3])
        : "r"(a0), "r"(a1), "r"(a2), "r"(a3), "r"(b0), "r"(b1));
}

// ---------------------------------------------------------------------------
// Kernel 1: modulate + demodulate -> tf32 weights in smem-ready layout
// ---------------------------------------------------------------------------
__global__ void modulate_kernel(const float* __restrict__ w,
                                const float* __restrict__ weight) {
    const int cout = blockIdx.x;
    const int b    = blockIdx.y;
    const int cin  = threadIdx.x;

    const float scale = 1.0f / 24.0f;  // 1/sqrt(64*9)
    const float wv = w[b * CINN + cin] * scale;

    float v[9];
    float ss = 0.0f;
#pragma unroll
    for (int kk = 0; kk < 9; ++kk) {
        float t = weight[(cout * CINN + cin) * 9 + kk] * wv;
        v[kk] = t;
        ss += t * t;
    }

    __shared__ float red[64];
    red[cin] = ss;
    __syncthreads();
    if (cin < 32) {
        float s = red[cin] + red[cin + 32];
#pragma unroll
        for (int off = 16; off > 0; off >>= 1)
            s += __shfl_down_sync(0xffffffffu, s, off);
        if (cin == 0) red[0] = s;
    }
    __syncthreads();

    const float d = rsqrtf(red[0] + 1e-8f);
    const int ch   = cin >> 3;
    const int j    = cin & 7;
    const int slot = 2 * (j & 3) + (j >> 2);   // k-index layout for tf32 mma frags
#pragma unroll
    for (int kk = 0; kk < 9; ++kk) {
        const uint32_t tv = f2tf32(v[kk] * d);
        g_wsw[((((size_t)b * 8 + ch) * 9 + kk) * COUTN + cout) * 8 + slot] =
            __uint_as_float(tv);
    }
}

// ---------------------------------------------------------------------------
// Kernel 2: TF32 mma.sync implicit-GEMM conv, cp.async double-buffered.
// grid (2, 512, 8), 256 threads (8 warps), 2 CTAs/SM.
// CTA tile: 64 couts x 256 pixels of one output row; K = 8 chunks x 9 taps x 8.
// ---------------------------------------------------------------------------
__global__ void __launch_bounds__(256, 2)
conv_mma_kernel(const float* __restrict__ x, float* __restrict__ out) {
    extern __shared__ char smem[];
    const uint32_t sbase = smem_u32(smem);

    const int b  = blockIdx.z;
    const int y  = blockIdx.y;
    const int x0 = blockIdx.x * SEG;

    const int tid    = threadIdx.x;
    const int wid    = tid >> 5;
    const int lane   = tid & 31;
    const int t      = lane & 3;
    const int g      = lane >> 2;
    const int warp_m = wid & 1;    // cout half
    const int warp_n = wid >> 1;   // pixel quarter

    float acc[2][8][4];
#pragma unroll
    for (int mt = 0; mt < 2; ++mt)
#pragma unroll
        for (int nt = 0; nt < 8; ++nt)
#pragma unroll
            for (int i = 0; i < 4; ++i) acc[mt][nt][i] = 0.0f;

    const int fill_slot = 2 * (wid & 3) + (wid >> 2);  // k-slot for this warp's cin plane

    // ---- stage fill: x tile (cp.async 4B + zfill) and weight tile (cp.async 16B)
    auto fill_stage = [&](int ch, int stage) {
        const uint32_t sx = sbase + stage * STAGE_BYTES;
        const uint32_t sw = sx + SX_BYTES;
        const int cb = ch * 8;

        // weights: straight 18432B copy, gmem layout == smem layout
        {
            const char* wsrc = (const char*)g_wsw + ((size_t)b * 8 + ch) * SW_BYTES;
#pragma unroll
            for (int k2 = 0; k2 < 5; ++k2) {
                const int idx = tid + k2 * 256;
                if (idx < SW_BYTES / 16) cp16(sw + idx * 16, wsrc + (size_t)idx * 16);
            }
        }

        // x: 3 rows x 8 cins (one cin per warp) x 258 px
#pragma unroll
        for (int row = 0; row < 3; ++row) {
            const int yy  = y + row - 1;
            const bool yok = ((unsigned)yy < (unsigned)HH);
            const float* src =
                x + ((size_t)(b * CINN + cb + wid) * HH + (yok ? yy : 0)) * WWW;
            const uint32_t dst0 = sx + (uint32_t)(row * 258 * 8 + fill_slot) * 4;
#pragma unroll
            for (int q = 0; q < 9; ++q) {
                const int px = lane + 32 * q;
                if (px < 258) {
                    const int gx = x0 - 1 + px;
                    const bool ok = yok && ((unsigned)gx < (unsigned)WWW);
                    const int gxc = gx < 0 ? 0 : (gx > WWW - 1 ? WWW - 1 : gx);
                    cp4(dst0 + (uint32_t)px * 32, src + gxc, ok ? 4u : 0u);
                }
            }
        }
    };

    // ---- compute one chunk from a stage ----
    auto compute_stage = [&](int stage) {
        const uint32_t sx = sbase + stage * STAGE_BYTES;
        const uint32_t sw = sx + SX_BYTES;
        const uint32_t awbase = sw + (uint32_t)(((warp_m * 32 + g) * 8) + 2 * t) * 4;
        const uint32_t abbase = sx + (uint32_t)(((warp_n * 64 + g) * 8) + 2 * t) * 4;

#pragma unroll
        for (int tap = 0; tap < 9; ++tap) {
            const int dy = tap / 3;
            const int dx = tap - dy * 3;
            const uint32_t aw = awbase + (uint32_t)tap * (64 * 32);
            const uint32_t ab = abbase + (uint32_t)(dy * 258 + dx) * 32;

            // A fragments (weights), 2 m-tiles: static offsets 0,256,512,768
            const float2 lo0 = lds64(aw);
            const float2 hi0 = lds64(aw + 8 * 32);
            const float2 lo1 = lds64(aw + 16 * 32);
            const float2 hi1 = lds64(aw + 24 * 32);
            const uint32_t A0[4] = {__float_as_uint(lo0.x), __float_as_uint(hi0.x),
                                    __float_as_uint(lo0.y), __float_as_uint(hi0.y)};
            const uint32_t A1[4] = {__float_as_uint(lo1.x), __float_as_uint(hi1.x),
                                    __float_as_uint(lo1.y), __float_as_uint(hi1.y)};

#pragma unroll
            for (int nt = 0; nt < 8; ++nt) {
                const float2 bb = lds64(ab + (uint32_t)nt * (8 * 32));
                const uint32_t b0 = __float_as_uint(bb.x);
                const uint32_t b1 = __float_as_uint(bb.y);
                mma_tf32(acc[0][nt], A0[0], A0[1], A0[2], A0[3], b0, b1);
                mma_tf32(acc[1][nt], A1[0], A1[1], A1[2], A1[3], b0, b1);
            }
        }
    };

    // ---- software pipeline: 2 stages in flight ----
    fill_stage(0, 0);
    cp_commit();
    fill_stage(1, 1);
    cp_commit();

#pragma unroll 1
    for (int ch = 0; ch < 8; ++ch) {
        if (ch < 7) cp_wait<1>(); else cp_wait<0>();
        __syncthreads();
        compute_stage(ch & 1);
        __syncthreads();
        if (ch + 2 < 8) {
            fill_stage(ch + 2, ch & 1);
            cp_commit();
        }
    }

    // ---- epilogue: float2 stores ----
#pragma unroll
    for (int mt = 0; mt < 2; ++mt) {
        const int cout0 = warp_m * 32 + mt * 16 + g;
#pragma unroll
        for (int nt = 0; nt < 8; ++nt) {
            const int px = x0 + warp_n * 64 + nt * 8 + 2 * t;
            float* p0 = out + (((size_t)(b * COUTN + cout0)) * HH + y) * WWW + px;
            float* p1 = out + (((size_t)(b * COUTN + cout0 + 8)) * HH + y) * WWW + px;
            *(float2*)p0 = make_float2(acc[mt][nt][0], acc[mt][nt][1]);
            *(float2*)p1 = make_float2(acc[mt][nt][2], acc[mt][nt][3]);
        }
    }
}

// ---------------------------------------------------------------------------
extern "C" void kernel_launch(void* const* d_in, const int* in_sizes, int n_in,
                              void* d_out, int out_size) {
    const float* x      = (const float*)d_in[0];   // [8,64,512,512]
    const float* w      = (const float*)d_in[1];   // [8,64]
    const float* weight = (const float*)d_in[2];   // [64,64,3,3]
    float* out = (float*)d_out;                    // [8,64,512,512]

    cudaFuncSetAttribute(conv_mma_kernel,
                         cudaFuncAttributeMaxDynamicSharedMemorySize, SMEM_DYN);

    modulate_kernel<<<dim3(COUTN, BB), 64>>>(w, weight);
    conv_mma_kernel<<<dim3(WWW / SEG, HH, BB), 256, SMEM_DYN>>>(x, out);
}

// round 5
// speedup vs baseline: 4.2515x; 1.0424x over previous
#include <cuda_runtime.h>
#include <cstdint>

// Problem constants
#define BB    8
#define CINN  64
#define COUTN 64
#define HH    512
#define WWW   512

#define SEG        256                  // output pixels per CTA
#define SX_BYTES   (3 * 258 * 8 * 4)    // 24768: 3 rows x 258 px x 8 k-slots
#define SW_BYTES   (9 * 64 * 8 * 4)     // 18432: 9 taps x 64 cout x 8 k-slots
#define STAGE_BYTES (SX_BYTES + SW_BYTES)  // 43200
#define SMEM_DYN   (2 * STAGE_BYTES)       // 86400

// Pre-demodulated tf32 weights, prearranged in smem layout:
// [b][ch(8)][tap(9)][cout(64)][slot(8)]   slot = 2*(j&3)+(j>>2), j = cin&7
__device__ float g_wsw[BB * 8 * 9 * COUTN * 8];

// ---------------------------------------------------------------------------
// helpers
// ---------------------------------------------------------------------------
__device__ __forceinline__ uint32_t smem_u32(const void* p) {
    uint32_t a;
    asm("{ .reg .u64 t; cvta.to.shared.u64 t, %1; cvt.u32.u64 %0, t; }" : "=r"(a) : "l"(p));
    return a;
}
__device__ __forceinline__ uint32_t f2tf32(float f) {
    uint32_t r;
    asm("cvt.rna.tf32.f32 %0, %1;" : "=r"(r) : "f"(f));
    return r;
}
__device__ __forceinline__ void cp16(uint32_t d, const void* s) {
    asm volatile("cp.async.cg.shared.global [%0], [%1], 16;" :: "r"(d), "l"(s) : "memory");
}
__device__ __forceinline__ void cp4(uint32_t d, const void* s, uint32_t sz) {
    asm volatile("cp.async.ca.shared.global [%0], [%1], 4, %2;"
                 :: "r"(d), "l"(s), "r"(sz) : "memory");
}
__device__ __forceinline__ void cp_commit() {
    asm volatile("cp.async.commit_group;" ::: "memory");
}
template <int N>
__device__ __forceinline__ void cp_wait() {
    asm volatile("cp.async.wait_group %0;" :: "n"(N) : "memory");
}
__device__ __forceinline__ float2 lds64(uint32_t a) {
    float2 v;
    asm volatile("ld.shared.v2.f32 {%0,%1}, [%2];" : "=f"(v.x), "=f"(v.y) : "r"(a));
    return v;
}
__device__ __forceinline__ void mma_tf32(float* d,
                                         uint32_t a0, uint32_t a1, uint32_t a2, uint32_t a3,
                                         uint32_t b0, uint32_t b1) {
    asm("mma.sync.aligned.m16n8k8.row.col.f32.tf32.tf32.f32 "
        "{%0,%1,%2,%3},{%4,%5,%6,%7},{%8,%9},{%0,%1,%2,%3};"
        : "+f"(d[0]), "+f"(d[1]), "+f"(d[2]), "+f"(d[3])
        : "r"(a0), "r"(a1), "r"(a2), "r"(a3), "r"(b0), "r"(b1));
}

// ---------------------------------------------------------------------------
// Kernel 1: modulate + demodulate -> tf32 weights in smem-ready layout
// ---------------------------------------------------------------------------
__global__ void modulate_kernel(const float* __restrict__ w,
                                const float* __restrict__ weight) {
    const int cout = blockIdx.x;
    const int b    = blockIdx.y;
    const int cin  = threadIdx.x;

    const float scale = 1.0f / 24.0f;  // 1/sqrt(64*9)
    const float wv = w[b * CINN + cin] * scale;

    float v[9];
    float ss = 0.0f;
#pragma unroll
    for (int kk = 0; kk < 9; ++kk) {
        float t = weight[(cout * CINN + cin) * 9 + kk] * wv;
        v[kk] = t;
        ss += t * t;
    }

    __shared__ float red[64];
    red[cin] = ss;
    __syncthreads();
    if (cin < 32) {
        float s = red[cin] + red[cin + 32];
#pragma unroll
        for (int off = 16; off > 0; off >>= 1)
            s += __shfl_down_sync(0xffffffffu, s, off);
        if (cin == 0) red[0] = s;
    }
    __syncthreads();

    const float d = rsqrtf(red[0] + 1e-8f);
    const int ch   = cin >> 3;
    const int j    = cin & 7;
    const int slot = 2 * (j & 3) + (j >> 2);   // k-index layout for tf32 mma frags
#pragma unroll
    for (int kk = 0; kk < 9; ++kk) {
        const uint32_t tv = f2tf32(v[kk] * d);
        g_wsw[((((size_t)b * 8 + ch) * 9 + kk) * COUTN + cout) * 8 + slot] =
            __uint_as_float(tv);
    }
}

// ---------------------------------------------------------------------------
// Kernel 2: TF32 mma.sync implicit-GEMM conv, cp.async double-buffered.
// grid (2, 512, 8), 128 threads (4 warps), 2 CTAs/SM.
// CTA tile: 64 couts x 256 pixels of one output row.
// Warp tile: 64 couts (4 m-tiles of 16) x 64 px (8 n-tiles of 8).
// K loop: 8 cin-chunks x 9 taps, K=8 per mma.
// ---------------------------------------------------------------------------
__global__ void __launch_bounds__(128, 2)
conv_mma_kernel(const float* __restrict__ x, float* __restrict__ out) {
    extern __shared__ char smem[];
    const uint32_t sbase = smem_u32(smem);

    const int b  = blockIdx.z;
    const int y  = blockIdx.y;
    const int x0 = blockIdx.x * SEG;

    const int tid    = threadIdx.x;
    const int wid    = tid >> 5;     // 0..3 = pixel quarter
    const int lane   = tid & 31;
    const int t      = lane & 3;
    const int g      = lane >> 2;

    float acc[4][8][4];
#pragma unroll
    for (int mt = 0; mt < 4; ++mt)
#pragma unroll
        for (int nt = 0; nt < 8; ++nt)
#pragma unroll
            for (int i = 0; i < 4; ++i) acc[mt][nt][i] = 0.0f;

    // ---- stage fill: x tile (cp.async 4B + zfill) and weight tile (cp.async 16B)
    auto fill_stage = [&](int ch, int stage) {
        const uint32_t sx = sbase + stage * STAGE_BYTES;
        const uint32_t sw = sx + SX_BYTES;
        const int cb = ch * 8;

        // weights: straight 18432B copy, gmem layout == smem layout
        {
            const char* wsrc = (const char*)g_wsw + ((size_t)b * 8 + ch) * SW_BYTES;
#pragma unroll
            for (int k2 = 0; k2 < 9; ++k2) {
                const int idx = tid + k2 * 128;
                cp16(sw + idx * 16, wsrc + (size_t)idx * 16);
            }
        }

        // x: 24 (row, cin) planes, one per warp round; 258 px each
#pragma unroll
        for (int pl = 0; pl < 6; ++pl) {
            const int plane = wid + pl * 4;       // 0..23
            const int row = plane >> 3;
            const int c   = plane & 7;
            const int slot = 2 * (c & 3) + (c >> 2);
            const int yy  = y + row - 1;
            const bool yok = ((unsigned)yy < (unsigned)HH);
            const float* src =
                x + ((size_t)(b * CINN + cb + c) * HH + (yok ? yy : 0)) * WWW;
            const uint32_t dst0 = sx + (uint32_t)(row * 258 * 8 + slot) * 4;
#pragma unroll
            for (int q = 0; q < 9; ++q) {
                const int px = lane + 32 * q;
                if (px < 258) {
                    const int gx = x0 - 1 + px;
                    const bool ok = yok && ((unsigned)gx < (unsigned)WWW);
                    const int gxc = gx < 0 ? 0 : (gx > WWW - 1 ? WWW - 1 : gx);
                    cp4(dst0 + (uint32_t)px * 32, src + gxc, ok ? 4u : 0u);
                }
            }
        }
    };

    // ---- compute one chunk from a stage ----
    auto compute_stage = [&](int stage) {
        const uint32_t sx = sbase + stage * STAGE_BYTES;
        const uint32_t sw = sx + SX_BYTES;
        const uint32_t awbase = sw + (uint32_t)((g * 8) + 2 * t) * 4;
        const uint32_t abbase = sx + (uint32_t)(((wid * 64 + g) * 8) + 2 * t) * 4;

#pragma unroll
        for (int tap = 0; tap < 9; ++tap) {
            const int dy = tap / 3;
            const int dx = tap - dy * 3;
            const uint32_t aw = awbase + (uint32_t)tap * (64 * 32);
            const uint32_t ab = abbase + (uint32_t)(dy * 258 + dx) * 32;

            // A fragments (weights), 4 m-tiles of 16 couts
            uint32_t A[4][4];
#pragma unroll
            for (int mt = 0; mt < 4; ++mt) {
                const float2 lo = lds64(aw + (uint32_t)(mt * 16) * 32);
                const float2 hi = lds64(aw + (uint32_t)(mt * 16 + 8) * 32);
                A[mt][0] = __float_as_uint(lo.x);
                A[mt][1] = __float_as_uint(hi.x);
                A[mt][2] = __float_as_uint(lo.y);
                A[mt][3] = __float_as_uint(hi.y);
            }

#pragma unroll
            for (int nt = 0; nt < 8; ++nt) {
                const float2 bb = lds64(ab + (uint32_t)nt * (8 * 32));
                const uint32_t b0 = __float_as_uint(bb.x);
                const uint32_t b1 = __float_as_uint(bb.y);
#pragma unroll
                for (int mt = 0; mt < 4; ++mt)
                    mma_tf32(acc[mt][nt], A[mt][0], A[mt][1], A[mt][2], A[mt][3],
                             b0, b1);
            }
        }
    };

    // ---- software pipeline: 2 stages in flight ----
    fill_stage(0, 0);
    cp_commit();
    fill_stage(1, 1);
    cp_commit();

#pragma unroll 1
    for (int ch = 0; ch < 8; ++ch) {
        if (ch < 7) cp_wait<1>(); else cp_wait<0>();
        __syncthreads();
        compute_stage(ch & 1);
        __syncthreads();
        if (ch + 2 < 8) {
            fill_stage(ch + 2, ch & 1);
            cp_commit();
        }
    }

    // ---- epilogue: float2 stores ----
#pragma unroll
    for (int mt = 0; mt < 4; ++mt) {
        const int cout0 = mt * 16 + g;
#pragma unroll
        for (int nt = 0; nt < 8; ++nt) {
            const int px = x0 + wid * 64 + nt * 8 + 2 * t;
            float* p0 = out + (((size_t)(b * COUTN + cout0)) * HH + y) * WWW + px;
            float* p1 = out + (((size_t)(b * COUTN + cout0 + 8)) * HH + y) * WWW + px;
            *(float2*)p0 = make_float2(acc[mt][nt][0], acc[mt][nt][1]);
            *(float2*)p1 = make_float2(acc[mt][nt][2], acc[mt][nt][3]);
        }
    }
}

// ---------------------------------------------------------------------------
extern "C" void kernel_launch(void* const* d_in, const int* in_sizes, int n_in,
                              void* d_out, int out_size) {
    const float* x      = (const float*)d_in[0];   // [8,64,512,512]
    const float* w      = (const float*)d_in[1];   // [8,64]
    const float* weight = (const float*)d_in[2];   // [64,64,3,3]
    float* out = (float*)d_out;                    // [8,64,512,512]

    cudaFuncSetAttribute(conv_mma_kernel,
                         cudaFuncAttributeMaxDynamicSharedMemorySize, SMEM_DYN);

    modulate_kernel<<<dim3(COUTN, BB), 64>>>(w, weight);
    conv_mma_kernel<<<dim3(WWW / SEG, HH, BB), 128, SMEM_DYN>>>(x, out);
}

// round 6
// speedup vs baseline: 7.6336x; 1.7955x over previous
#include <cuda_runtime.h>
#include <cuda_fp16.h>
#include <cstdint>

// Problem constants
#define BB    8
#define CINN  64
#define COUTN 64
#define HH    512
#define WWW   512

#define SEG        256                    // output pixels per CTA
#define NCH        4                      // cin chunks of 16
#define SX_BYTES   (3 * 258 * 32)         // 24768: 3 rows x 258 px x 16 fp16
#define SW_BYTES   (9 * 64 * 32)          // 18432: 9 taps x 64 cout x 16 fp16
#define STAGE_BYTES (SX_BYTES + SW_BYTES) // 43200
#define SMEM_DYN   (2 * STAGE_BYTES)      // 86400

// x transposed+converted: [b][y][w][64 cins fp16], cins slot-interleaved
// per 16-chunk: slot(j) = 4*((j>>1)&3) + (j&1) + 2*(j>>3)
__device__ __half g_xh[(size_t)BB * HH * WWW * CINN];
// demodulated fp16 weights: [b][ch(4)][tap(9)][cout(64)][slot(16)]
__device__ __half g_wsh[BB * NCH * 9 * COUTN * 16];

// ---------------------------------------------------------------------------
// helpers
// ---------------------------------------------------------------------------
__device__ __forceinline__ uint32_t smem_u32(const void* p) {
    uint32_t a;
    asm("{ .reg .u64 t; cvta.to.shared.u64 t, %1; cvt.u32.u64 %0, t; }" : "=r"(a) : "l"(p));
    return a;
}
__device__ __forceinline__ void cp16(uint32_t d, const void* s) {
    asm volatile("cp.async.cg.shared.global [%0], [%1], 16;" :: "r"(d), "l"(s) : "memory");
}
__device__ __forceinline__ void cp16z(uint32_t d, const void* s, uint32_t sz) {
    asm volatile("cp.async.cg.shared.global [%0], [%1], 16, %2;"
                 :: "r"(d), "l"(s), "r"(sz) : "memory");
}
__device__ __forceinline__ void cp_commit() {
    asm volatile("cp.async.commit_group;" ::: "memory");
}
template <int N>
__device__ __forceinline__ void cp_wait() {
    asm volatile("cp.async.wait_group %0;" :: "n"(N) : "memory");
}
__device__ __forceinline__ uint2 lds64(uint32_t a) {
    uint2 v;
    asm volatile("ld.shared.v2.u32 {%0,%1}, [%2];" : "=r"(v.x), "=r"(v.y) : "r"(a));
    return v;
}
__device__ __forceinline__ void mma_f16(float* d,
                                        uint32_t a0, uint32_t a1, uint32_t a2, uint32_t a3,
                                        uint32_t b0, uint32_t b1) {
    asm("mma.sync.aligned.m16n8k16.row.col.f32.f16.f16.f32 "
        "{%0,%1,%2,%3},{%4,%5,%6,%7},{%8,%9},{%0,%1,%2,%3};"
        : "+f"(d[0]), "+f"(d[1]), "+f"(d[2]), "+f"(d[3])
        : "r"(a0), "r"(a1), "r"(a2), "r"(a3), "r"(b0), "r"(b1));
}

// slot within a 16-cin chunk for mma k-fragment order {2t,2t+1,2t+8,2t+9}
__device__ __forceinline__ int kslot(int j) {
    return 4 * ((j >> 1) & 3) + (j & 1) + 2 * (j >> 3);
}

// ---------------------------------------------------------------------------
// Kernel 0: transpose + fp16-convert x -> g_xh[b][y][w][64] (slot-interleaved)
// grid (16, 512, 8), 256 threads; tile = 32 px x 64 cins.
// ---------------------------------------------------------------------------
__global__ void __launch_bounds__(256)
transpose_kernel(const float* __restrict__ x) {
    __shared__ __half s[64][33];

    const int b  = blockIdx.z;
    const int y  = blockIdx.y;
    const int x0 = blockIdx.x * 32;
    const int tid  = threadIdx.x;
    const int wid  = tid >> 5;
    const int lane = tid & 31;

    // read: 8 rounds, warp w reads cin = wid + 8*it, 32 consecutive px
#pragma unroll
    for (int it = 0; it < 8; ++it) {
        const int cin = wid + it * 8;
        const float v = x[(((size_t)(b * CINN + cin) * HH) + y) * WWW + x0 + lane];
        s[cin][lane] = __float2half_rn(v);
    }
    __syncthreads();

    // write: thread -> (px = tid>>3, group = tid&7), 8 halves (16B) per thread
    const int px    = tid >> 3;
    const int group = tid & 7;
    ushort h[8];
#pragma unroll
    for (int k = 0; k < 8; ++k) {
        const int hidx = group * 8 + k;        // 0..63 target half index
        const int ch16 = hidx >> 4;
        const int sidx = hidx & 15;            // slot within chunk
        const int tloc = sidx >> 2;
        const int w    = sidx & 3;
        const int cin  = ch16 * 16 + 2 * tloc + (w & 1) + 8 * (w >> 1);
        h[k] = __half_as_ushort(s[cin][px]);
    }
    uint4 v;
    v.x = (uint32_t)h[0] | ((uint32_t)h[1] << 16);
    v.y = (uint32_t)h[2] | ((uint32_t)h[3] << 16);
    v.z = (uint32_t)h[4] | ((uint32_t)h[5] << 16);
    v.w = (uint32_t)h[6] | ((uint32_t)h[7] << 16);
    __half* dst = g_xh + ((((size_t)b * HH + y) * WWW) + x0 + px) * CINN + group * 8;
    *reinterpret_cast<uint4*>(dst) = v;
}

// ---------------------------------------------------------------------------
// Kernel 1: modulate + demodulate -> fp16 weights in smem-ready layout
// ---------------------------------------------------------------------------
__global__ void modulate_kernel(const float* __restrict__ w,
                                const float* __restrict__ weight) {
    const int cout = blockIdx.x;
    const int b    = blockIdx.y;
    const int cin  = threadIdx.x;

    const float scale = 1.0f / 24.0f;  // 1/sqrt(64*9)
    const float wv = w[b * CINN + cin] * scale;

    float v[9];
    float ss = 0.0f;
#pragma unroll
    for (int kk = 0; kk < 9; ++kk) {
        float t = weight[(cout * CINN + cin) * 9 + kk] * wv;
        v[kk] = t;
        ss += t * t;
    }

    __shared__ float red[64];
    red[cin] = ss;
    __syncthreads();
    if (cin < 32) {
        float s = red[cin] + red[cin + 32];
#pragma unroll
        for (int off = 16; off > 0; off >>= 1)
            s += __shfl_down_sync(0xffffffffu, s, off);
        if (cin == 0) red[0] = s;
    }
    __syncthreads();

    const float d = rsqrtf(red[0] + 1e-8f);
    const int ch   = cin >> 4;
    const int slot = kslot(cin & 15);
#pragma unroll
    for (int kk = 0; kk < 9; ++kk) {
        g_wsh[((((size_t)b * NCH + ch) * 9 + kk) * COUTN + cout) * 16 + slot] =
            __float2half_rn(v[kk] * d);
    }
}

// ---------------------------------------------------------------------------
// Kernel 2: FP16 mma.sync (m16n8k16) implicit-GEMM conv, cp.async pipelined.
// grid (2, 512, 8), 128 threads (4 warps), 2 CTAs/SM.
// CTA tile: 64 couts x 256 pixels of one output row.
// Warp tile: 64 couts (4 m-tiles of 16) x 64 px (8 n-tiles of 8).
// K loop: 4 cin-chunks of 16 x 9 taps, K=16 per mma.
// ---------------------------------------------------------------------------
__global__ void __launch_bounds__(128, 2)
conv_mma_kernel(float* __restrict__ out) {
    extern __shared__ char smem[];
    const uint32_t sbase = smem_u32(smem);

    const int b  = blockIdx.z;
    const int y  = blockIdx.y;
    const int x0 = blockIdx.x * SEG;

    const int tid  = threadIdx.x;
    const int wid  = tid >> 5;     // pixel quarter
    const int lane = tid & 31;
    const int t    = lane & 3;
    const int g    = lane >> 2;

    float acc[4][8][4];
#pragma unroll
    for (int mt = 0; mt < 4; ++mt)
#pragma unroll
        for (int nt = 0; nt < 8; ++nt)
#pragma unroll
            for (int i = 0; i < 4; ++i) acc[mt][nt][i] = 0.0f;

    // ---- stage fill: all cp.async 16B ----
    auto fill_stage = [&](int ch, int stage) {
        const uint32_t sx = sbase + stage * STAGE_BYTES;
        const uint32_t sw = sx + SX_BYTES;

        // weights: straight 18432B copy (gmem layout == smem layout)
        {
            const char* wsrc = (const char*)g_wsh + ((size_t)b * NCH + ch) * SW_BYTES;
#pragma unroll
            for (int k2 = 0; k2 < 9; ++k2) {
                const int idx = tid + k2 * 128;
                cp16(sw + idx * 16, wsrc + (size_t)idx * 16);
            }
        }

        // x: 3 rows x 258 px x 32B (two 16B copies per px), zfill halo
#pragma unroll
        for (int row = 0; row < 3; ++row) {
            const int yy  = y + row - 1;
            const bool yok = ((unsigned)yy < (unsigned)HH);
            const __half* src =
                g_xh + (((size_t)b * HH + (yok ? yy : 0)) * WWW) * CINN + ch * 16;
            const uint32_t dst0 = sx + (uint32_t)row * (258 * 32);
#pragma unroll
            for (int i = tid; i < 516; i += 128) {
                const int px   = i >> 1;
                const int half = i & 1;
                const int gx   = x0 - 1 + px;
                const bool ok  = yok && ((unsigned)gx < (unsigned)WWW);
                const int gxc  = gx < 0 ? 0 : (gx > WWW - 1 ? WWW - 1 : gx);
                cp16z(dst0 + (uint32_t)px * 32 + half * 16,
                      src + (size_t)gxc * CINN + half * 8, ok ? 16u : 0u);
            }
        }
    };

    // ---- compute one 16-cin chunk from a stage ----
    auto compute_stage = [&](int stage) {
        const uint32_t sx = sbase + stage * STAGE_BYTES;
        const uint32_t sw = sx + SX_BYTES;
        const uint32_t awbase = sw + (uint32_t)(g * 32 + t * 8);
        const uint32_t abbase = sx + (uint32_t)((wid * 64 + g) * 32 + t * 8);

#pragma unroll
        for (int tap = 0; tap < 9; ++tap) {
            const int dy = tap / 3;
            const int dx = tap - dy * 3;
            const uint32_t aw = awbase + (uint32_t)tap * (64 * 32);
            const uint32_t ab = abbase + (uint32_t)(dy * 258 + dx) * 32;

            // A fragments: 4 m-tiles of 16 couts, 2x LDS.64 each
            uint32_t A[4][4];
#pragma unroll
            for (int mt = 0; mt < 4; ++mt) {
                const uint2 lo = lds64(aw + (uint32_t)(mt * 16) * 32);
                const uint2 hi = lds64(aw + (uint32_t)(mt * 16 + 8) * 32);
                A[mt][0] = lo.x;   // (row g,   k 2t..2t+1)
                A[mt][1] = hi.x;   // (row g+8, k 2t..2t+1)
                A[mt][2] = lo.y;   // (row g,   k 2t+8..2t+9)
                A[mt][3] = hi.y;   // (row g+8, k 2t+8..2t+9)
            }

#pragma unroll
            for (int nt = 0; nt < 8; ++nt) {
                const uint2 bb = lds64(ab + (uint32_t)nt * (8 * 32));
#pragma unroll
                for (int mt = 0; mt < 4; ++mt)
                    mma_f16(acc[mt][nt], A[mt][0], A[mt][1], A[mt][2], A[mt][3],
                            bb.x, bb.y);
            }
        }
    };

    // ---- software pipeline: 2 stages in flight over 4 chunks ----
    fill_stage(0, 0);
    cp_commit();
    fill_stage(1, 1);
    cp_commit();

#pragma unroll 1
    for (int ch = 0; ch < NCH; ++ch) {
        if (ch < NCH - 1) cp_wait<1>(); else cp_wait<0>();
        __syncthreads();
        compute_stage(ch & 1);
        __syncthreads();
        if (ch + 2 < NCH) {
            fill_stage(ch + 2, ch & 1);
            cp_commit();
        }
    }

    // ---- epilogue: float2 stores ----
#pragma unroll
    for (int mt = 0; mt < 4; ++mt) {
        const int cout0 = mt * 16 + g;
#pragma unroll
        for (int nt = 0; nt < 8; ++nt) {
            const int px = x0 + wid * 64 + nt * 8 + 2 * t;
            float* p0 = out + (((size_t)(b * COUTN + cout0)) * HH + y) * WWW + px;
            float* p1 = out + (((size_t)(b * COUTN + cout0 + 8)) * HH + y) * WWW + px;
            *(float2*)p0 = make_float2(acc[mt][nt][0], acc[mt][nt][1]);
            *(float2*)p1 = make_float2(acc[mt][nt][2], acc[mt][nt][3]);
        }
    }
}

// ---------------------------------------------------------------------------
extern "C" void kernel_launch(void* const* d_in, const int* in_sizes, int n_in,
                              void* d_out, int out_size) {
    const float* x      = (const float*)d_in[0];   // [8,64,512,512]
    const float* w      = (const float*)d_in[1];   // [8,64]
    const float* weight = (const float*)d_in[2];   // [64,64,3,3]
    float* out = (float*)d_out;                    // [8,64,512,512]

    cudaFuncSetAttribute(conv_mma_kernel,
                         cudaFuncAttributeMaxDynamicSharedMemorySize, SMEM_DYN);

    transpose_kernel<<<dim3(WWW / 32, HH, BB), 256>>>(x);
    modulate_kernel<<<dim3(COUTN, BB), 64>>>(w, weight);
    conv_mma_kernel<<<dim3(WWW / SEG, HH, BB), 128, SMEM_DYN>>>(out);
}